// round 11
// baseline (speedup 1.0000x reference)
#include <cuda_runtime.h>
#include <cstdint>
#include <cstddef>

#define SQ 512      // sequence length
#define BQ 128      // batch
#define EV 100      // embedding dim
#define HDQ 64      // per-direction hidden
#define G4 256      // 4*HD gates
#define TK 9        // tagset-1
#define NSEG 32     // CRF scan segments (16 steps each)

typedef unsigned long long ull;

// ---------------- scratch (device globals: allocation-free rule) ----------------
__device__ float g_preF[(size_t)SQ * BQ * G4];   // 64MB  fwd input projections
__device__ float g_preB[(size_t)SQ * BQ * G4];   // 64MB  bwd input projections
// +16 zero rows of padding so the CRF scan prefetch never branches (exp(0)=1).
// Pad rows are never written -> stay zero across graph replays.
__device__ float g_em[(size_t)(SQ + 16) * BQ * TK];
__device__ float g_segM[(size_t)BQ * NSEG * 81]; // per-segment 9x9 product matrices
__device__ int   g_segE[BQ * NSEG];              // per-segment power-of-2 exponents
__device__ float g_loss[BQ];

__device__ __forceinline__ float tanhfast(float x) {
    float y;
    asm("tanh.approx.f32 %0, %1;" : "=f"(y) : "f"(x));
    return y;
}
__device__ __forceinline__ ull fma2(ull a, ull b, ull c) {
    ull d;
    asm("fma.rn.f32x2 %0, %1, %2, %3;" : "=l"(d) : "l"(a), "l"(b), "l"(c));
    return d;
}
__device__ __forceinline__ ull splat2(float x) {
    ull d; unsigned u = __float_as_uint(x);
    asm("mov.b64 %0, {%1, %1};" : "=l"(d) : "r"(u));
    return d;
}
__device__ __forceinline__ float2 unpack2(ull v) {
    unsigned lo, hi;
    asm("mov.b64 {%0, %1}, %2;" : "=r"(lo), "=r"(hi) : "l"(v));
    return make_float2(__uint_as_float(lo), __uint_as_float(hi));
}

// ---------------- kernel 1: embedding gather + input projection GEMM (R5 scalar) ----------------
__global__ __launch_bounds__(256) void k_embed_gemm(
    const int* __restrict__ inputs, const float* __restrict__ emb,
    const float* __restrict__ WihF, const float* __restrict__ WihB)
{
    __shared__ __align__(16) float As[20][68];
    __shared__ __align__(16) float Bs[20][68];
    __shared__ int tok[64];
    const int tid = threadIdx.x;
    const int m0 = blockIdx.x * 64;
    const int n0 = blockIdx.y * 64;
    const int dir = (n0 >= 256);
    const float* __restrict__ W = dir ? WihB : WihF;
    const int nl0 = n0 & 255;
    float* __restrict__ out = dir ? g_preB : g_preF;

    if (tid < 64) {
        int m = m0 + tid;
        int s = m >> 7, b = m & 127;
        tok[tid] = inputs[b * SQ + s];
    }
    __syncthreads();

    ull accp[2][4] = {};
    const int tx = tid & 15, ty = tid >> 4;

    for (int kc = 0; kc < 5; kc++) {
        const int k0 = kc * 20;
#pragma unroll
        for (int i = 0; i < 5; i++) {
            int idx = tid + i * 256;
            int r = idx / 20, kk = idx - r * 20;
            As[kk][r] = emb[(size_t)tok[r] * EV + k0 + kk];
            Bs[kk][r] = W[(nl0 + r) * EV + k0 + kk];
        }
        __syncthreads();
#pragma unroll
        for (int k = 0; k < 20; k++) {
            ulonglong2 a2 = *(const ulonglong2*)&As[k][ty * 4];
            float4 bv = *(const float4*)&Bs[k][tx * 4];
            ull b0 = splat2(bv.x), b1 = splat2(bv.y);
            ull b2 = splat2(bv.z), b3 = splat2(bv.w);
            accp[0][0] = fma2(a2.x, b0, accp[0][0]);
            accp[0][1] = fma2(a2.x, b1, accp[0][1]);
            accp[0][2] = fma2(a2.x, b2, accp[0][2]);
            accp[0][3] = fma2(a2.x, b3, accp[0][3]);
            accp[1][0] = fma2(a2.y, b0, accp[1][0]);
            accp[1][1] = fma2(a2.y, b1, accp[1][1]);
            accp[1][2] = fma2(a2.y, b2, accp[1][2]);
            accp[1][3] = fma2(a2.y, b3, accp[1][3]);
        }
        __syncthreads();
    }
#pragma unroll
    for (int i2 = 0; i2 < 2; i2++) {
        float2 c0 = unpack2(accp[i2][0]);
        float2 c1 = unpack2(accp[i2][1]);
        float2 c2 = unpack2(accp[i2][2]);
        float2 c3 = unpack2(accp[i2][3]);
        int m = m0 + ty * 4 + i2 * 2;
        *(float4*)&out[(size_t)m * G4 + nl0 + tx * 4] =
            make_float4(c0.x, c1.x, c2.x, c3.x);
        *(float4*)&out[(size_t)(m + 1) * G4 + nl0 + tx * 4] =
            make_float4(c0.y, c1.y, c2.y, c3.y);
    }
}

// ---------------- kernel 2: bidirectional LSTM + fused emissions ----------------
// R5 structure. Emission fusion: after each step's h is published in h_sh,
// 72 lanes (warps 4-6) compute the 9 emission dot-products for their dir's s.
// For any s, the FIRST writer is the dir reaching it at step t<256 (identical
// condition for both dirs); it stores bias+partial. The second (t>=256) does
// read-add-write. Ordering is guaranteed by the per-step __syncthreads.
__global__ __launch_bounds__(512, 1) void k_lstm(
    const float* __restrict__ WhhF, const float* __restrict__ WhhB,
    const float* __restrict__ bF, const float* __restrict__ bB,
    const float* __restrict__ Wout, const float* __restrict__ bout)
{
    __shared__ __align__(16) float h_sh[2][128];  // [buf][dir*64 + j]
    const int tid = threadIdx.x;
    const int b = blockIdx.x;
    const int dir = tid >> 8;
    const int q = tid & 255;
    const int j = q >> 2;
    const int gt = q & 3;
    const int rowidx = (gt << 6) | j;

    const float* __restrict__ Wr = (dir ? WhhB : WhhF) + rowidx * HDQ;
    ull w2[32];
#pragma unroll
    for (int i = 0; i < 32; i++) w2[i] = ((const ull*)Wr)[i];
    const float bias = (dir ? bB : bF)[rowidx];
    const float* __restrict__ pre = dir ? g_preB : g_preF;

    // --- emission-fusion setup: warps 4..6 (tid 128..223), 72 active slots ---
    const int et = tid - 128;                    // [0,96) for warps 4-6
    const bool emw = (et >= 0 && et < 96);       // whole warps execute (shfl-safe)
    const int ec = (et < 72 && et >= 0) ? et : 0; // clamped slot
    const int ed = ec / 36;                      // emission dir
    const int er = ec - ed * 36;
    const int ej = er >> 2;                      // output tag 0..8
    const int ecx = er & 3;                      // 16-h chunk 0..3
    ull ew2[8];
    float ebias = 0.f;
    if (emw) {
        const float* wp = Wout + (size_t)(ej + 1) * 128 + (ed << 6) + (ecx << 4);
#pragma unroll
        for (int i = 0; i < 8; i++) ew2[i] = ((const ull*)wp)[i];
        ebias = bout[ej + 1];
    }

    float c = 0.f;
    if (tid < 128) h_sh[0][tid] = 0.f;
    __syncthreads();

    const int base = dir << 6;
    const int lane = tid & 31;
    const int lb = lane & ~3;

    float nxt[4];
#pragma unroll
    for (int k = 0; k < 4; k++) {
        int s = dir ? (SQ - 1 - k) : k;
        nxt[k] = pre[((size_t)s * BQ + b) * G4 + rowidx];
    }

    for (int t0 = 0; t0 < SQ; t0 += 4) {
#pragma unroll
        for (int k = 0; k < 4; k++) {
            const int t = t0 + k;
            float cur = nxt[k];
            int tp = t + 4;
            if (tp < SQ) {
                int sn = dir ? (SQ - 1 - tp) : tp;
                nxt[k] = pre[((size_t)sn * BQ + b) * G4 + rowidx];
            }
            const ulonglong2* hp = (const ulonglong2*)(h_sh[t & 1] + base);
            ull a0 = 0, a1 = 0, a2p = 0, a3p = 0;
#pragma unroll
            for (int kk = 0; kk < 8; kk++) {
                ulonglong2 h01 = hp[2 * kk];
                ulonglong2 h23 = hp[2 * kk + 1];
                a0 = fma2(h01.x, w2[4 * kk + 0], a0);
                a1 = fma2(h01.y, w2[4 * kk + 1], a1);
                a2p = fma2(h23.x, w2[4 * kk + 2], a2p);
                a3p = fma2(h23.y, w2[4 * kk + 3], a3p);
            }
            float2 p0 = unpack2(a0), p1 = unpack2(a1);
            float2 p2 = unpack2(a2p), p3 = unpack2(a3p);
            float a = cur + bias + ((p0.x + p0.y) + (p1.x + p1.y))
                                 + ((p2.x + p2.y) + (p3.x + p3.y));
            float av = (gt == 2) ? tanhfast(a)
                                 : (0.5f * tanhfast(0.5f * a) + 0.5f);
            float af = __shfl_sync(0xffffffffu, av, lb | 1, 32);
            float ag = __shfl_sync(0xffffffffu, av, lb | 2, 32);
            float ao = __shfl_sync(0xffffffffu, av, lb | 3, 32);
            if (gt == 0) {
                c = af * c + av * ag;
                float h = ao * tanhfast(c);
                h_sh[(t + 1) & 1][base | j] = h;
            }
            __syncthreads();

            // ---- fused emission for this step (h of step t is in buf (t+1)&1)
            if (emw) {
                const ull* hp2 =
                    (const ull*)(h_sh[(t + 1) & 1] + (ed << 6) + (ecx << 4));
                ull eacc = 0;
#pragma unroll
                for (int i = 0; i < 8; i++) eacc = fma2(hp2[i], ew2[i], eacc);
                float2 pp = unpack2(eacc);
                float part = pp.x + pp.y;
                part += __shfl_down_sync(0xffffffffu, part, 2);
                part += __shfl_down_sync(0xffffffffu, part, 1);
                if (et < 72 && ecx == 0) {
                    int s_ = ed ? (SQ - 1 - t) : t;
                    size_t ei = ((size_t)s_ * BQ + b) * TK + ej;
                    float basev = ebias;
                    if (t >= 256) basev = g_em[ei];   // second writer: accumulate
                    g_em[ei] = basev + part;
                }
            }
        }
    }
}

// ---------------- kernel 4a: CRF segment scan (32 segments x 16 steps) ----------------
__global__ __launch_bounds__(32) void k_crf_seg(const float* __restrict__ trans)
{
    const int b = blockIdx.x;
    const int seg = blockIdx.y;
    const int lane = threadIdx.x;
    const bool act = lane < 9;
    const unsigned FULL = 0xffffffffu;

    float Pc[9];
#pragma unroll
    for (int i = 0; i < 9; i++)
        Pc[i] = act ? __expf(trans[i * 9 + lane]) : 0.f;

    const int t0 = 1 + (seg << 4);
    const int nst = (seg == NSEG - 1) ? 15 : 16;

    float w[4];
#pragma unroll
    for (int k = 0; k < 4; k++)
        w[k] = __expf(act ? g_em[((size_t)(t0 + k) * BQ + b) * TK + lane] : 0.f);

    float A[9];
#pragma unroll
    for (int i = 0; i < 9; i++) A[i] = Pc[i] * w[0];   // M_{t0}
    int eacc = 0;

    for (int sidx = 1; sidx < nst; sidx++) {
        float C[9] = {0.f, 0.f, 0.f, 0.f, 0.f, 0.f, 0.f, 0.f, 0.f};
#pragma unroll
        for (int k = 0; k < 9; k++) {
            float pk = Pc[k];
            C[0] = fmaf(__shfl_sync(FULL, A[0], k), pk, C[0]);
            C[1] = fmaf(__shfl_sync(FULL, A[1], k), pk, C[1]);
            C[2] = fmaf(__shfl_sync(FULL, A[2], k), pk, C[2]);
            C[3] = fmaf(__shfl_sync(FULL, A[3], k), pk, C[3]);
            C[4] = fmaf(__shfl_sync(FULL, A[4], k), pk, C[4]);
            C[5] = fmaf(__shfl_sync(FULL, A[5], k), pk, C[5]);
            C[6] = fmaf(__shfl_sync(FULL, A[6], k), pk, C[6]);
            C[7] = fmaf(__shfl_sync(FULL, A[7], k), pk, C[7]);
            C[8] = fmaf(__shfl_sync(FULL, A[8], k), pk, C[8]);
        }
        float wt = w[sidx & 3];
#pragma unroll
        for (int i = 0; i < 9; i++) A[i] = C[i] * wt;
        w[sidx & 3] =
            __expf(act ? g_em[((size_t)(t0 + sidx + 4) * BQ + b) * TK + lane] : 0.f);
        if ((sidx & 7) == 0) {
            float r = __shfl_sync(FULL, A[0], 0);
            int e = ((__float_as_int(r) >> 23) & 255) - 127;
            float sc = __int_as_float((127 - e) << 23);
#pragma unroll
            for (int i = 0; i < 9; i++) A[i] *= sc;
            eacc += e;
        }
    }

    const size_t mo = (size_t)(b * NSEG + seg) * 81;
    if (act) {
#pragma unroll
        for (int i = 0; i < 9; i++) g_segM[mo + i * 9 + lane] = A[i];
    }
    if (lane == 0) g_segE[b * NSEG + seg] = eacc;
}

// ---------------- kernel 4b: CRF combine + gold score ----------------
__global__ __launch_bounds__(32) void k_crf_fin(
    const int* __restrict__ tags, const float* __restrict__ start,
    const float* __restrict__ endv, const float* __restrict__ trans)
{
    const int b = blockIdx.x;
    const int lane = threadIdx.x;
    const bool act = lane < 9;
    const unsigned FULL = 0xffffffffu;

    float u = act ? __expf(start[lane] + g_em[(size_t)b * TK + lane]) : 0.f;
    int eacc = 0;

    for (int seg = 0; seg < NSEG; seg++) {
        const size_t mo = (size_t)(b * NSEG + seg) * 81;
        float Mc[9];
#pragma unroll
        for (int i = 0; i < 9; i++)
            Mc[i] = act ? g_segM[mo + i * 9 + lane] : 0.f;
        eacc += g_segE[b * NSEG + seg];
        float nu = 0.f;
#pragma unroll
        for (int i = 0; i < 9; i++)
            nu = fmaf(__shfl_sync(FULL, u, i), Mc[i], nu);
        u = nu;
        float r = __shfl_sync(FULL, u, 0);
        int e = ((__float_as_int(r) >> 23) & 255) - 127;
        u *= __int_as_float((127 - e) << 23);
        eacc += e;
    }

    float v = act ? u * __expf(endv[lane]) : 0.f;
#pragma unroll
    for (int off = 16; off; off >>= 1) v += __shfl_down_sync(FULL, v, off);
    float logZ = 0.f;
    if (lane == 0) logZ = __logf(v) + (float)eacc * 0.6931471805599453f;

    const int* __restrict__ tg = tags + (size_t)b * SQ;
    float sc = 0.f;
    for (int t = 1 + lane; t < SQ; t += 32) {
        int tp = tg[t - 1] - 1, tcr = tg[t] - 1;
        sc += trans[tp * 9 + tcr] + g_em[((size_t)t * BQ + b) * TK + tcr];
    }
#pragma unroll
    for (int off = 16; off; off >>= 1) sc += __shfl_down_sync(FULL, sc, off);
    if (lane == 0) {
        int t0 = tg[0] - 1, tl = tg[SQ - 1] - 1;
        sc += start[t0] + g_em[(size_t)b * TK + t0] + endv[tl];
        g_loss[b] = logZ - sc;
    }
}

// ---------------- kernel 5: deterministic reduction ----------------
__global__ __launch_bounds__(128) void k_reduce(float* __restrict__ out)
{
    __shared__ float sm[128];
    const int tid = threadIdx.x;
    sm[tid] = g_loss[tid];
    __syncthreads();
    for (int off = 64; off; off >>= 1) {
        if (tid < off) sm[tid] += sm[tid + off];
        __syncthreads();
    }
    if (tid == 0) out[0] = sm[0] * (1.0f / 128.0f);
}

// ---------------- launcher ----------------
extern "C" void kernel_launch(void* const* d_in, const int* in_sizes, int n_in,
                              void* d_out, int out_size)
{
    const int*   inputs = (const int*)d_in[0];
    const int*   tags   = (const int*)d_in[1];
    // d_in[2] = mask (all ones by construction)
    const float* emb    = (const float*)d_in[3];
    const float* Wih_f  = (const float*)d_in[4];
    const float* Whh_f  = (const float*)d_in[5];
    const float* b_f    = (const float*)d_in[6];
    const float* Wih_b  = (const float*)d_in[7];
    const float* Whh_b  = (const float*)d_in[8];
    const float* b_b    = (const float*)d_in[9];
    const float* W_out  = (const float*)d_in[10];
    const float* b_out  = (const float*)d_in[11];
    const float* start  = (const float*)d_in[12];
    const float* endv   = (const float*)d_in[13];
    const float* trans  = (const float*)d_in[14];
    float* out = (float*)d_out;

    dim3 gemm_grid(1024, 8);
    k_embed_gemm<<<gemm_grid, 256>>>(inputs, emb, Wih_f, Wih_b);
    k_lstm<<<128, 512>>>(Whh_f, Whh_b, b_f, b_b, W_out, b_out);
    dim3 seg_grid(BQ, NSEG);
    k_crf_seg<<<seg_grid, 32>>>(trans);
    k_crf_fin<<<BQ, 32>>>(tags, start, endv, trans);
    k_reduce<<<1, 128>>>(out);
}

// round 12
// speedup vs baseline: 1.1551x; 1.1551x over previous
#include <cuda_runtime.h>
#include <cstdint>
#include <cstddef>

#define SQ 512      // sequence length
#define BQ 128      // batch
#define EV 100      // embedding dim
#define HDQ 64      // per-direction hidden
#define G4 256      // 4*HD gates
#define TK 9        // tagset-1
#define NSEG 16     // CRF scan segments (32 steps each)

typedef unsigned long long ull;

// ---------------- scratch (device globals: allocation-free rule) ----------------
__device__ float g_preF[(size_t)SQ * BQ * G4];   // 64MB  fwd input projections
__device__ float g_preB[(size_t)SQ * BQ * G4];   // 64MB  bwd input projections
__device__ float g_hall[(size_t)SQ * BQ * 128];  // 32MB  concat hidden [s][b][128]
// +16 zero rows of padding so the CRF scan prefetch never branches (exp(0)=1)
__device__ float g_em[(size_t)(SQ + 16) * BQ * TK];
__device__ float g_segM[(size_t)BQ * NSEG * 81]; // per-segment 9x9 product matrices
__device__ int   g_segE[BQ * NSEG];              // per-segment power-of-2 exponents
__device__ float g_loss[BQ];
__device__ float g_dummy[32];                    // sink for no-op launches

__device__ __forceinline__ float tanhfast(float x) {
    float y;
    asm("tanh.approx.f32 %0, %1;" : "=f"(y) : "f"(x));
    return y;
}
__device__ __forceinline__ ull fma2(ull a, ull b, ull c) {
    ull d;
    asm("fma.rn.f32x2 %0, %1, %2, %3;" : "=l"(d) : "l"(a), "l"(b), "l"(c));
    return d;
}
__device__ __forceinline__ ull splat2(float x) {
    ull d; unsigned u = __float_as_uint(x);
    asm("mov.b64 %0, {%1, %1};" : "=l"(d) : "r"(u));
    return d;
}
__device__ __forceinline__ float2 unpack2(ull v) {
    unsigned lo, hi;
    asm("mov.b64 {%0, %1}, %2;" : "=r"(lo), "=r"(hi) : "l"(v));
    return make_float2(__uint_as_float(lo), __uint_as_float(hi));
}

// ---------------- kernel 0: no-op (shifts the ncu capture window) ----------------
__global__ __launch_bounds__(32) void k_nop()
{
    if (threadIdx.x < 32) g_dummy[threadIdx.x] = (float)threadIdx.x;
}

// ---------------- kernel 1: embedding gather + input projection GEMM (R5 scalar) ----------------
__global__ __launch_bounds__(256) void k_embed_gemm(
    const int* __restrict__ inputs, const float* __restrict__ emb,
    const float* __restrict__ WihF, const float* __restrict__ WihB)
{
    __shared__ __align__(16) float As[20][68];
    __shared__ __align__(16) float Bs[20][68];
    __shared__ int tok[64];
    const int tid = threadIdx.x;
    const int m0 = blockIdx.x * 64;
    const int n0 = blockIdx.y * 64;
    const int dir = (n0 >= 256);
    const float* __restrict__ W = dir ? WihB : WihF;
    const int nl0 = n0 & 255;
    float* __restrict__ out = dir ? g_preB : g_preF;

    if (tid < 64) {
        int m = m0 + tid;
        int s = m >> 7, b = m & 127;
        tok[tid] = inputs[b * SQ + s];
    }
    __syncthreads();

    ull accp[2][4] = {};
    const int tx = tid & 15, ty = tid >> 4;

    for (int kc = 0; kc < 5; kc++) {
        const int k0 = kc * 20;
#pragma unroll
        for (int i = 0; i < 5; i++) {
            int idx = tid + i * 256;
            int r = idx / 20, kk = idx - r * 20;
            As[kk][r] = emb[(size_t)tok[r] * EV + k0 + kk];
            Bs[kk][r] = W[(nl0 + r) * EV + k0 + kk];
        }
        __syncthreads();
#pragma unroll
        for (int k = 0; k < 20; k++) {
            ulonglong2 a2 = *(const ulonglong2*)&As[k][ty * 4];
            float4 bv = *(const float4*)&Bs[k][tx * 4];
            ull b0 = splat2(bv.x), b1 = splat2(bv.y);
            ull b2 = splat2(bv.z), b3 = splat2(bv.w);
            accp[0][0] = fma2(a2.x, b0, accp[0][0]);
            accp[0][1] = fma2(a2.x, b1, accp[0][1]);
            accp[0][2] = fma2(a2.x, b2, accp[0][2]);
            accp[0][3] = fma2(a2.x, b3, accp[0][3]);
            accp[1][0] = fma2(a2.y, b0, accp[1][0]);
            accp[1][1] = fma2(a2.y, b1, accp[1][1]);
            accp[1][2] = fma2(a2.y, b2, accp[1][2]);
            accp[1][3] = fma2(a2.y, b3, accp[1][3]);
        }
        __syncthreads();
    }
#pragma unroll
    for (int i2 = 0; i2 < 2; i2++) {
        float2 c0 = unpack2(accp[i2][0]);
        float2 c1 = unpack2(accp[i2][1]);
        float2 c2 = unpack2(accp[i2][2]);
        float2 c3 = unpack2(accp[i2][3]);
        int m = m0 + ty * 4 + i2 * 2;
        *(float4*)&out[(size_t)m * G4 + nl0 + tx * 4] =
            make_float4(c0.x, c1.x, c2.x, c3.x);
        *(float4*)&out[(size_t)(m + 1) * G4 + nl0 + tx * 4] =
            make_float4(c0.y, c1.y, c2.y, c3.y);
    }
}

// ---------------- kernel 2: bidirectional LSTM recurrence ----------------
// R8 logic, but fwd/bwd split into separate blocks: 256 blocks = (b, dir),
// 256 threads = (unit j, gate gt). The two chains share nothing — separate
// blocks decouple their barriers and let their stalls overlap on one SM.
__global__ __launch_bounds__(256, 2) void k_lstm(
    const float* __restrict__ WhhF, const float* __restrict__ WhhB,
    const float* __restrict__ bF, const float* __restrict__ bB)
{
    __shared__ __align__(16) float h_sh[2][64];
    const int tid = threadIdx.x;
    const int b = blockIdx.x >> 1;
    const int dir = blockIdx.x & 1;
    const int j = tid >> 2;
    const int gt = tid & 3;                 // 0:i 1:f 2:g 3:o
    const int rowidx = (gt << 6) | j;

    const float* __restrict__ Wr = (dir ? WhhB : WhhF) + rowidx * HDQ;
    ull w2[32];
#pragma unroll
    for (int i = 0; i < 32; i++) w2[i] = ((const ull*)Wr)[i];
    const float bias = (dir ? bB : bF)[rowidx];
    const float* __restrict__ pre = dir ? g_preB : g_preF;

    float c = 0.f;
    if (tid < 64) h_sh[0][tid] = 0.f;
    __syncthreads();

    const int lane = tid & 31;
    const int lb = lane & ~3;

    float nxt[4];
#pragma unroll
    for (int k = 0; k < 4; k++) {
        int s = dir ? (SQ - 1 - k) : k;
        nxt[k] = pre[((size_t)s * BQ + b) * G4 + rowidx];
    }

    for (int t0 = 0; t0 < SQ; t0 += 4) {
#pragma unroll
        for (int k = 0; k < 4; k++) {
            const int t = t0 + k;
            float cur = nxt[k];
            int tp = t + 4;
            if (tp < SQ) {
                int sn = dir ? (SQ - 1 - tp) : tp;
                nxt[k] = pre[((size_t)sn * BQ + b) * G4 + rowidx];
            }
            const ulonglong2* hp = (const ulonglong2*)h_sh[t & 1];
            ull a0 = 0, a1 = 0, a2p = 0, a3p = 0;
#pragma unroll
            for (int kk = 0; kk < 8; kk++) {
                ulonglong2 h01 = hp[2 * kk];
                ulonglong2 h23 = hp[2 * kk + 1];
                a0 = fma2(h01.x, w2[4 * kk + 0], a0);
                a1 = fma2(h01.y, w2[4 * kk + 1], a1);
                a2p = fma2(h23.x, w2[4 * kk + 2], a2p);
                a3p = fma2(h23.y, w2[4 * kk + 3], a3p);
            }
            float2 p0 = unpack2(a0), p1 = unpack2(a1);
            float2 p2 = unpack2(a2p), p3 = unpack2(a3p);
            float a = cur + bias + ((p0.x + p0.y) + (p1.x + p1.y))
                                 + ((p2.x + p2.y) + (p3.x + p3.y));
            float av = (gt == 2) ? tanhfast(a)
                                 : (0.5f * tanhfast(0.5f * a) + 0.5f);
            float af = __shfl_sync(0xffffffffu, av, lb | 1, 32);
            float ag = __shfl_sync(0xffffffffu, av, lb | 2, 32);
            float ao = __shfl_sync(0xffffffffu, av, lb | 3, 32);
            if (gt == 0) {
                c = af * c + av * ag;
                float h = ao * tanhfast(c);
                h_sh[(t + 1) & 1][j] = h;
                int s = dir ? (SQ - 1 - t) : t;
                g_hall[((size_t)s * BQ + b) * 128 + (dir << 6) + j] = h;
            }
            __syncthreads();
        }
    }
}

// ---------------- kernel 3: emissions (R5) ----------------
__global__ __launch_bounds__(128) void k_emis(
    const float* __restrict__ Wout, const float* __restrict__ bout)
{
    __shared__ __align__(16) float hs[16][132];
    __shared__ __align__(16) float ws[9][132];
    __shared__ float bs[9];
    const int tid = threadIdx.x;
    const size_t m0 = (size_t)blockIdx.x * 16;
#pragma unroll
    for (int i = 0; i < 16; i++) {
        int idx = tid + i * 128;
        hs[idx >> 7][idx & 127] = g_hall[m0 * 128 + idx];
    }
    for (int idx = tid; idx < 9 * 128; idx += 128)
        ws[idx >> 7][idx & 127] = Wout[128 + idx];  // rows 1..9
    if (tid < 9) bs[tid] = bout[tid + 1];
    __syncthreads();

    for (int o = tid; o < 144; o += 128) {
        int r = o / 9, jj = o - r * 9;
        const ull* hp = (const ull*)&hs[r][0];
        const ull* wp = (const ull*)&ws[jj][0];
        ull acc2 = 0;
#pragma unroll
        for (int k = 0; k < 64; k++) acc2 = fma2(hp[k], wp[k], acc2);
        float2 p = unpack2(acc2);
        g_em[(m0 + r) * TK + jj] = bs[jj] + p.x + p.y;
    }
}

// ---------------- kernel 4a: CRF segment scan (16 segments x 32 steps, R8) ----------------
__global__ __launch_bounds__(32) void k_crf_seg(const float* __restrict__ trans)
{
    const int b = blockIdx.x;
    const int seg = blockIdx.y;
    const int lane = threadIdx.x;
    const bool act = lane < 9;
    const unsigned FULL = 0xffffffffu;

    float Pc[9];
#pragma unroll
    for (int i = 0; i < 9; i++)
        Pc[i] = act ? __expf(trans[i * 9 + lane]) : 0.f;

    const int t0 = 1 + (seg << 5);
    const int nst = (seg == NSEG - 1) ? 31 : 32;

    float w[4];
#pragma unroll
    for (int k = 0; k < 4; k++)
        w[k] = __expf(act ? g_em[((size_t)(t0 + k) * BQ + b) * TK + lane] : 0.f);

    float A[9];
#pragma unroll
    for (int i = 0; i < 9; i++) A[i] = Pc[i] * w[0];   // M_{t0}
    int eacc = 0;

    for (int sidx = 1; sidx < nst; sidx++) {
        float C[9] = {0.f, 0.f, 0.f, 0.f, 0.f, 0.f, 0.f, 0.f, 0.f};
#pragma unroll
        for (int k = 0; k < 9; k++) {
            float pk = Pc[k];
            C[0] = fmaf(__shfl_sync(FULL, A[0], k), pk, C[0]);
            C[1] = fmaf(__shfl_sync(FULL, A[1], k), pk, C[1]);
            C[2] = fmaf(__shfl_sync(FULL, A[2], k), pk, C[2]);
            C[3] = fmaf(__shfl_sync(FULL, A[3], k), pk, C[3]);
            C[4] = fmaf(__shfl_sync(FULL, A[4], k), pk, C[4]);
            C[5] = fmaf(__shfl_sync(FULL, A[5], k), pk, C[5]);
            C[6] = fmaf(__shfl_sync(FULL, A[6], k), pk, C[6]);
            C[7] = fmaf(__shfl_sync(FULL, A[7], k), pk, C[7]);
            C[8] = fmaf(__shfl_sync(FULL, A[8], k), pk, C[8]);
        }
        float wt = w[sidx & 3];
#pragma unroll
        for (int i = 0; i < 9; i++) A[i] = C[i] * wt;
        w[sidx & 3] =
            __expf(act ? g_em[((size_t)(t0 + sidx + 4) * BQ + b) * TK + lane] : 0.f);
        if ((sidx & 7) == 0) {
            float r = __shfl_sync(FULL, A[0], 0);
            int e = ((__float_as_int(r) >> 23) & 255) - 127;
            float sc = __int_as_float((127 - e) << 23);
#pragma unroll
            for (int i = 0; i < 9; i++) A[i] *= sc;
            eacc += e;
        }
    }

    const size_t mo = (size_t)(b * NSEG + seg) * 81;
    if (act) {
#pragma unroll
        for (int i = 0; i < 9; i++) g_segM[mo + i * 9 + lane] = A[i];
    }
    if (lane == 0) g_segE[b * NSEG + seg] = eacc;
}

// ---------------- kernel 4b: CRF combine + gold score (R8) ----------------
__global__ __launch_bounds__(32) void k_crf_fin(
    const int* __restrict__ tags, const float* __restrict__ start,
    const float* __restrict__ endv, const float* __restrict__ trans)
{
    const int b = blockIdx.x;
    const int lane = threadIdx.x;
    const bool act = lane < 9;
    const unsigned FULL = 0xffffffffu;

    float u = act ? __expf(start[lane] + g_em[(size_t)b * TK + lane]) : 0.f;
    int eacc = 0;

    for (int seg = 0; seg < NSEG; seg++) {
        const size_t mo = (size_t)(b * NSEG + seg) * 81;
        float Mc[9];
#pragma unroll
        for (int i = 0; i < 9; i++)
            Mc[i] = act ? g_segM[mo + i * 9 + lane] : 0.f;
        eacc += g_segE[b * NSEG + seg];
        float nu = 0.f;
#pragma unroll
        for (int i = 0; i < 9; i++)
            nu = fmaf(__shfl_sync(FULL, u, i), Mc[i], nu);
        u = nu;
        float r = __shfl_sync(FULL, u, 0);
        int e = ((__float_as_int(r) >> 23) & 255) - 127;
        u *= __int_as_float((127 - e) << 23);
        eacc += e;
    }

    float v = act ? u * __expf(endv[lane]) : 0.f;
#pragma unroll
    for (int off = 16; off; off >>= 1) v += __shfl_down_sync(FULL, v, off);
    float logZ = 0.f;
    if (lane == 0) logZ = __logf(v) + (float)eacc * 0.6931471805599453f;

    const int* __restrict__ tg = tags + (size_t)b * SQ;
    float sc = 0.f;
    for (int t = 1 + lane; t < SQ; t += 32) {
        int tp = tg[t - 1] - 1, tcr = tg[t] - 1;
        sc += trans[tp * 9 + tcr] + g_em[((size_t)t * BQ + b) * TK + tcr];
    }
#pragma unroll
    for (int off = 16; off; off >>= 1) sc += __shfl_down_sync(FULL, sc, off);
    if (lane == 0) {
        int t0 = tg[0] - 1, tl = tg[SQ - 1] - 1;
        sc += start[t0] + g_em[(size_t)b * TK + t0] + endv[tl];
        g_loss[b] = logZ - sc;
    }
}

// ---------------- kernel 5: deterministic reduction ----------------
__global__ __launch_bounds__(128) void k_reduce(float* __restrict__ out)
{
    __shared__ float sm[128];
    const int tid = threadIdx.x;
    sm[tid] = g_loss[tid];
    __syncthreads();
    for (int off = 64; off; off >>= 1) {
        if (tid < off) sm[tid] += sm[tid + off];
        __syncthreads();
    }
    if (tid == 0) out[0] = sm[0] * (1.0f / 128.0f);
}

// ---------------- launcher ----------------
extern "C" void kernel_launch(void* const* d_in, const int* in_sizes, int n_in,
                              void* d_out, int out_size)
{
    const int*   inputs = (const int*)d_in[0];
    const int*   tags   = (const int*)d_in[1];
    // d_in[2] = mask (all ones by construction)
    const float* emb    = (const float*)d_in[3];
    const float* Wih_f  = (const float*)d_in[4];
    const float* Whh_f  = (const float*)d_in[5];
    const float* b_f    = (const float*)d_in[6];
    const float* Wih_b  = (const float*)d_in[7];
    const float* Whh_b  = (const float*)d_in[8];
    const float* b_b    = (const float*)d_in[9];
    const float* W_out  = (const float*)d_in[10];
    const float* b_out  = (const float*)d_in[11];
    const float* start  = (const float*)d_in[12];
    const float* endv   = (const float*)d_in[13];
    const float* trans  = (const float*)d_in[14];
    float* out = (float*)d_out;

    // Two no-op launches shift the ncu capture window (launch index 3)
    // onto k_lstm — the dominant, never-yet-profiled kernel.
    k_nop<<<1, 32>>>();
    k_nop<<<1, 32>>>();
    dim3 gemm_grid(1024, 8);
    k_embed_gemm<<<gemm_grid, 256>>>(inputs, emb, Wih_f, Wih_b);
    k_lstm<<<256, 256>>>(Whh_f, Whh_b, b_f, b_b);
    k_emis<<<4096, 128>>>(W_out, b_out);
    dim3 seg_grid(BQ, NSEG);
    k_crf_seg<<<seg_grid, 32>>>(trans);
    k_crf_fin<<<BQ, 32>>>(tags, start, endv, trans);
    k_reduce<<<1, 128>>>(out);
}

// round 13
// speedup vs baseline: 1.1976x; 1.0367x over previous
#include <cuda_runtime.h>
#include <cstdint>
#include <cstddef>

#define SQ 512      // sequence length
#define BQ 128      // batch
#define EV 100      // embedding dim
#define HDQ 64      // per-direction hidden
#define G4 256      // 4*HD gates
#define TK 9        // tagset-1
#define NSEG 16     // CRF scan segments (32 steps each)

typedef unsigned long long ull;

// ---------------- scratch (device globals: allocation-free rule) ----------------
// pre buffers padded +4 time rows: the LSTM 4-deep prefetch reads rows
// SQ..SQ+3 (never consumed). g_preB is stored TIME-REVERSED by the GEMM so
// both directions stream strictly forward with one advancing pointer.
__device__ float g_preF[(size_t)(SQ + 4) * BQ * G4];
__device__ float g_preB[(size_t)(SQ + 4) * BQ * G4];
__device__ float g_hall[(size_t)SQ * BQ * 128];  // concat hidden [s][b][128]
// +16 zero rows of padding so the CRF scan prefetch never branches (exp(0)=1)
__device__ float g_em[(size_t)(SQ + 16) * BQ * TK];
__device__ float g_segM[(size_t)BQ * NSEG * 81]; // per-segment 9x9 product matrices
__device__ int   g_segE[BQ * NSEG];              // per-segment power-of-2 exponents
__device__ float g_loss[BQ];
__device__ float g_dummy[32];                    // sink for no-op launches

__device__ __forceinline__ float tanhfast(float x) {
    float y;
    asm("tanh.approx.f32 %0, %1;" : "=f"(y) : "f"(x));
    return y;
}
__device__ __forceinline__ ull fma2(ull a, ull b, ull c) {
    ull d;
    asm("fma.rn.f32x2 %0, %1, %2, %3;" : "=l"(d) : "l"(a), "l"(b), "l"(c));
    return d;
}
__device__ __forceinline__ ull splat2(float x) {
    ull d; unsigned u = __float_as_uint(x);
    asm("mov.b64 %0, {%1, %1};" : "=l"(d) : "r"(u));
    return d;
}
__device__ __forceinline__ float2 unpack2(ull v) {
    unsigned lo, hi;
    asm("mov.b64 {%0, %1}, %2;" : "=r"(lo), "=r"(hi) : "l"(v));
    return make_float2(__uint_as_float(lo), __uint_as_float(hi));
}

// ---------------- kernel 0: no-op (shifts the ncu capture window) ----------------
__global__ __launch_bounds__(32) void k_nop()
{
    if (threadIdx.x < 32) g_dummy[threadIdx.x] = (float)threadIdx.x;
}

// ---------------- kernel 1: embedding gather + input projection GEMM ----------------
// R5 scalar core; backward-direction output stored time-reversed (row SQ-1-s).
__global__ __launch_bounds__(256) void k_embed_gemm(
    const int* __restrict__ inputs, const float* __restrict__ emb,
    const float* __restrict__ WihF, const float* __restrict__ WihB)
{
    __shared__ __align__(16) float As[20][68];
    __shared__ __align__(16) float Bs[20][68];
    __shared__ int tok[64];
    const int tid = threadIdx.x;
    const int m0 = blockIdx.x * 64;
    const int n0 = blockIdx.y * 64;
    const int dir = (n0 >= 256);
    const float* __restrict__ W = dir ? WihB : WihF;
    const int nl0 = n0 & 255;
    float* __restrict__ out = dir ? g_preB : g_preF;

    if (tid < 64) {
        int m = m0 + tid;
        int s = m >> 7, b = m & 127;
        tok[tid] = inputs[b * SQ + s];
    }
    __syncthreads();

    ull accp[2][4] = {};
    const int tx = tid & 15, ty = tid >> 4;

    for (int kc = 0; kc < 5; kc++) {
        const int k0 = kc * 20;
#pragma unroll
        for (int i = 0; i < 5; i++) {
            int idx = tid + i * 256;
            int r = idx / 20, kk = idx - r * 20;
            As[kk][r] = emb[(size_t)tok[r] * EV + k0 + kk];
            Bs[kk][r] = W[(nl0 + r) * EV + k0 + kk];
        }
        __syncthreads();
#pragma unroll
        for (int k = 0; k < 20; k++) {
            ulonglong2 a2 = *(const ulonglong2*)&As[k][ty * 4];
            float4 bv = *(const float4*)&Bs[k][tx * 4];
            ull b0 = splat2(bv.x), b1 = splat2(bv.y);
            ull b2 = splat2(bv.z), b3 = splat2(bv.w);
            accp[0][0] = fma2(a2.x, b0, accp[0][0]);
            accp[0][1] = fma2(a2.x, b1, accp[0][1]);
            accp[0][2] = fma2(a2.x, b2, accp[0][2]);
            accp[0][3] = fma2(a2.x, b3, accp[0][3]);
            accp[1][0] = fma2(a2.y, b0, accp[1][0]);
            accp[1][1] = fma2(a2.y, b1, accp[1][1]);
            accp[1][2] = fma2(a2.y, b2, accp[1][2]);
            accp[1][3] = fma2(a2.y, b3, accp[1][3]);
        }
        __syncthreads();
    }
    // whole 64-row tile lies within one time step s
    const int s = m0 >> 7;
    const size_t orow = dir ? ((size_t)(SQ - 1 - s) * BQ) : ((size_t)s * BQ);
#pragma unroll
    for (int i2 = 0; i2 < 2; i2++) {
        float2 c0 = unpack2(accp[i2][0]);
        float2 c1 = unpack2(accp[i2][1]);
        float2 c2 = unpack2(accp[i2][2]);
        float2 c3 = unpack2(accp[i2][3]);
        int bb = (m0 & 127) + ty * 4 + i2 * 2;
        *(float4*)&out[(orow + bb) * G4 + nl0 + tx * 4] =
            make_float4(c0.x, c1.x, c2.x, c3.x);
        *(float4*)&out[(orow + bb + 1) * G4 + nl0 + tx * 4] =
            make_float4(c0.y, c1.y, c2.y, c3.y);
    }
}

// ---------------- kernel 2: bidirectional LSTM recurrence ----------------
// 256 blocks = (b, dir), 256 threads = (unit j, gate gt). Branch-free
// streaming: padded pre + time-reversed preB -> one advancing pointer,
// no guard, no per-step IMAD chain.
__global__ __launch_bounds__(256, 2) void k_lstm(
    const float* __restrict__ WhhF, const float* __restrict__ WhhB,
    const float* __restrict__ bF, const float* __restrict__ bB)
{
    __shared__ __align__(16) float h_sh[2][64];
    const int tid = threadIdx.x;
    const int b = blockIdx.x >> 1;
    const int dir = blockIdx.x & 1;
    const int j = tid >> 2;
    const int gt = tid & 3;                 // 0:i 1:f 2:g 3:o
    const int rowidx = (gt << 6) | j;
    const ptrdiff_t STRIDE = (ptrdiff_t)BQ * G4;

    const float* __restrict__ Wr = (dir ? WhhB : WhhF) + rowidx * HDQ;
    ull w2[32];
#pragma unroll
    for (int i = 0; i < 32; i++) w2[i] = ((const ull*)Wr)[i];
    const float bias = (dir ? bB : bF)[rowidx];
    const float* __restrict__ pre = dir ? g_preB : g_preF;

    float c = 0.f;
    if (tid < 64) h_sh[0][tid] = 0.f;
    __syncthreads();

    const int lane = tid & 31;
    const int lb = lane & ~3;

    // prefetch ring + advancing load pointer (rows 4..SQ+3; pads never used)
    const float* P = pre + (size_t)b * G4 + rowidx;
    float nxt[4];
#pragma unroll
    for (int k = 0; k < 4; k++) { nxt[k] = *P; P += STRIDE; }

    // advancing store pointer for g_hall (cell lanes only)
    float* hout = g_hall + (size_t)(dir ? (SQ - 1) : 0) * BQ * 128
                + (size_t)b * 128 + (dir << 6) + j;
    const ptrdiff_t HSTRIDE = dir ? -(ptrdiff_t)(BQ * 128) : (ptrdiff_t)(BQ * 128);

    for (int t0 = 0; t0 < SQ; t0 += 4) {
#pragma unroll
        for (int k = 0; k < 4; k++) {
            const int t = t0 + k;
            float cur = nxt[k];
            nxt[k] = *P; P += STRIDE;            // padded: always safe
            const ulonglong2* hp = (const ulonglong2*)h_sh[t & 1];
            ull a0 = 0, a1 = 0, a2p = 0, a3p = 0;
#pragma unroll
            for (int kk = 0; kk < 8; kk++) {
                ulonglong2 h01 = hp[2 * kk];
                ulonglong2 h23 = hp[2 * kk + 1];
                a0 = fma2(h01.x, w2[4 * kk + 0], a0);
                a1 = fma2(h01.y, w2[4 * kk + 1], a1);
                a2p = fma2(h23.x, w2[4 * kk + 2], a2p);
                a3p = fma2(h23.y, w2[4 * kk + 3], a3p);
            }
            float2 p0 = unpack2(a0), p1 = unpack2(a1);
            float2 p2 = unpack2(a2p), p3 = unpack2(a3p);
            float a = cur + bias + ((p0.x + p0.y) + (p1.x + p1.y))
                                 + ((p2.x + p2.y) + (p3.x + p3.y));
            float av = (gt == 2) ? tanhfast(a)
                                 : (0.5f * tanhfast(0.5f * a) + 0.5f);
            float af = __shfl_sync(0xffffffffu, av, lb | 1, 32);
            float ag = __shfl_sync(0xffffffffu, av, lb | 2, 32);
            float ao = __shfl_sync(0xffffffffu, av, lb | 3, 32);
            if (gt == 0) {
                c = af * c + av * ag;
                float h = ao * tanhfast(c);
                h_sh[(t + 1) & 1][j] = h;
                *hout = h;
            }
            hout += HSTRIDE;
            __syncthreads();
        }
    }
}

// ---------------- kernel 3: emissions (R5) ----------------
__global__ __launch_bounds__(128) void k_emis(
    const float* __restrict__ Wout, const float* __restrict__ bout)
{
    __shared__ __align__(16) float hs[16][132];
    __shared__ __align__(16) float ws[9][132];
    __shared__ float bs[9];
    const int tid = threadIdx.x;
    const size_t m0 = (size_t)blockIdx.x * 16;
#pragma unroll
    for (int i = 0; i < 16; i++) {
        int idx = tid + i * 128;
        hs[idx >> 7][idx & 127] = g_hall[m0 * 128 + idx];
    }
    for (int idx = tid; idx < 9 * 128; idx += 128)
        ws[idx >> 7][idx & 127] = Wout[128 + idx];  // rows 1..9
    if (tid < 9) bs[tid] = bout[tid + 1];
    __syncthreads();

    for (int o = tid; o < 144; o += 128) {
        int r = o / 9, jj = o - r * 9;
        const ull* hp = (const ull*)&hs[r][0];
        const ull* wp = (const ull*)&ws[jj][0];
        ull acc2 = 0;
#pragma unroll
        for (int k = 0; k < 64; k++) acc2 = fma2(hp[k], wp[k], acc2);
        float2 p = unpack2(acc2);
        g_em[(m0 + r) * TK + jj] = bs[jj] + p.x + p.y;
    }
}

// ---------------- kernel 4a: CRF segment scan (16 segments x 32 steps, R8) ----------------
__global__ __launch_bounds__(32) void k_crf_seg(const float* __restrict__ trans)
{
    const int b = blockIdx.x;
    const int seg = blockIdx.y;
    const int lane = threadIdx.x;
    const bool act = lane < 9;
    const unsigned FULL = 0xffffffffu;

    float Pc[9];
#pragma unroll
    for (int i = 0; i < 9; i++)
        Pc[i] = act ? __expf(trans[i * 9 + lane]) : 0.f;

    const int t0 = 1 + (seg << 5);
    const int nst = (seg == NSEG - 1) ? 31 : 32;

    float w[4];
#pragma unroll
    for (int k = 0; k < 4; k++)
        w[k] = __expf(act ? g_em[((size_t)(t0 + k) * BQ + b) * TK + lane] : 0.f);

    float A[9];
#pragma unroll
    for (int i = 0; i < 9; i++) A[i] = Pc[i] * w[0];   // M_{t0}
    int eacc = 0;

    for (int sidx = 1; sidx < nst; sidx++) {
        float C[9] = {0.f, 0.f, 0.f, 0.f, 0.f, 0.f, 0.f, 0.f, 0.f};
#pragma unroll
        for (int k = 0; k < 9; k++) {
            float pk = Pc[k];
            C[0] = fmaf(__shfl_sync(FULL, A[0], k), pk, C[0]);
            C[1] = fmaf(__shfl_sync(FULL, A[1], k), pk, C[1]);
            C[2] = fmaf(__shfl_sync(FULL, A[2], k), pk, C[2]);
            C[3] = fmaf(__shfl_sync(FULL, A[3], k), pk, C[3]);
            C[4] = fmaf(__shfl_sync(FULL, A[4], k), pk, C[4]);
            C[5] = fmaf(__shfl_sync(FULL, A[5], k), pk, C[5]);
            C[6] = fmaf(__shfl_sync(FULL, A[6], k), pk, C[6]);
            C[7] = fmaf(__shfl_sync(FULL, A[7], k), pk, C[7]);
            C[8] = fmaf(__shfl_sync(FULL, A[8], k), pk, C[8]);
        }
        float wt = w[sidx & 3];
#pragma unroll
        for (int i = 0; i < 9; i++) A[i] = C[i] * wt;
        w[sidx & 3] =
            __expf(act ? g_em[((size_t)(t0 + sidx + 4) * BQ + b) * TK + lane] : 0.f);
        if ((sidx & 7) == 0) {
            float r = __shfl_sync(FULL, A[0], 0);
            int e = ((__float_as_int(r) >> 23) & 255) - 127;
            float sc = __int_as_float((127 - e) << 23);
#pragma unroll
            for (int i = 0; i < 9; i++) A[i] *= sc;
            eacc += e;
        }
    }

    const size_t mo = (size_t)(b * NSEG + seg) * 81;
    if (act) {
#pragma unroll
        for (int i = 0; i < 9; i++) g_segM[mo + i * 9 + lane] = A[i];
    }
    if (lane == 0) g_segE[b * NSEG + seg] = eacc;
}

// ---------------- kernel 4b: CRF combine + gold score (R8) ----------------
__global__ __launch_bounds__(32) void k_crf_fin(
    const int* __restrict__ tags, const float* __restrict__ start,
    const float* __restrict__ endv, const float* __restrict__ trans)
{
    const int b = blockIdx.x;
    const int lane = threadIdx.x;
    const bool act = lane < 9;
    const unsigned FULL = 0xffffffffu;

    float u = act ? __expf(start[lane] + g_em[(size_t)b * TK + lane]) : 0.f;
    int eacc = 0;

    for (int seg = 0; seg < NSEG; seg++) {
        const size_t mo = (size_t)(b * NSEG + seg) * 81;
        float Mc[9];
#pragma unroll
        for (int i = 0; i < 9; i++)
            Mc[i] = act ? g_segM[mo + i * 9 + lane] : 0.f;
        eacc += g_segE[b * NSEG + seg];
        float nu = 0.f;
#pragma unroll
        for (int i = 0; i < 9; i++)
            nu = fmaf(__shfl_sync(FULL, u, i), Mc[i], nu);
        u = nu;
        float r = __shfl_sync(FULL, u, 0);
        int e = ((__float_as_int(r) >> 23) & 255) - 127;
        u *= __int_as_float((127 - e) << 23);
        eacc += e;
    }

    float v = act ? u * __expf(endv[lane]) : 0.f;
#pragma unroll
    for (int off = 16; off; off >>= 1) v += __shfl_down_sync(FULL, v, off);
    float logZ = 0.f;
    if (lane == 0) logZ = __logf(v) + (float)eacc * 0.6931471805599453f;

    const int* __restrict__ tg = tags + (size_t)b * SQ;
    float sc = 0.f;
    for (int t = 1 + lane; t < SQ; t += 32) {
        int tp = tg[t - 1] - 1, tcr = tg[t] - 1;
        sc += trans[tp * 9 + tcr] + g_em[((size_t)t * BQ + b) * TK + tcr];
    }
#pragma unroll
    for (int off = 16; off; off >>= 1) sc += __shfl_down_sync(FULL, sc, off);
    if (lane == 0) {
        int t0 = tg[0] - 1, tl = tg[SQ - 1] - 1;
        sc += start[t0] + g_em[(size_t)b * TK + t0] + endv[tl];
        g_loss[b] = logZ - sc;
    }
}

// ---------------- kernel 5: deterministic reduction ----------------
__global__ __launch_bounds__(128) void k_reduce(float* __restrict__ out)
{
    __shared__ float sm[128];
    const int tid = threadIdx.x;
    sm[tid] = g_loss[tid];
    __syncthreads();
    for (int off = 64; off; off >>= 1) {
        if (tid < off) sm[tid] += sm[tid + off];
        __syncthreads();
    }
    if (tid == 0) out[0] = sm[0] * (1.0f / 128.0f);
}

// ---------------- launcher ----------------
extern "C" void kernel_launch(void* const* d_in, const int* in_sizes, int n_in,
                              void* d_out, int out_size)
{
    const int*   inputs = (const int*)d_in[0];
    const int*   tags   = (const int*)d_in[1];
    // d_in[2] = mask (all ones by construction)
    const float* emb    = (const float*)d_in[3];
    const float* Wih_f  = (const float*)d_in[4];
    const float* Whh_f  = (const float*)d_in[5];
    const float* b_f    = (const float*)d_in[6];
    const float* Wih_b  = (const float*)d_in[7];
    const float* Whh_b  = (const float*)d_in[8];
    const float* b_b    = (const float*)d_in[9];
    const float* W_out  = (const float*)d_in[10];
    const float* b_out  = (const float*)d_in[11];
    const float* start  = (const float*)d_in[12];
    const float* endv   = (const float*)d_in[13];
    const float* trans  = (const float*)d_in[14];
    float* out = (float*)d_out;

    // Three no-op launches shift the ncu capture window (launch index 3)
    // onto k_embed_gemm — the last major unprofiled kernel.
    k_nop<<<1, 32>>>();
    k_nop<<<1, 32>>>();
    k_nop<<<1, 32>>>();
    dim3 gemm_grid(1024, 8);
    k_embed_gemm<<<gemm_grid, 256>>>(inputs, emb, Wih_f, Wih_b);
    k_lstm<<<256, 256>>>(Whh_f, Whh_b, b_f, b_b);
    k_emis<<<4096, 128>>>(W_out, b_out);
    dim3 seg_grid(BQ, NSEG);
    k_crf_seg<<<seg_grid, 32>>>(trans);
    k_crf_fin<<<BQ, 32>>>(tags, start, endv, trans);
    k_reduce<<<1, 128>>>(out);
}